// round 1
// baseline (speedup 1.0000x reference)
#include <cuda_runtime.h>

#define Hd 128
#define Nn 512
#define Bb 2
#define TJ 32
#define NT 256

// Scratch (no allocations allowed)
__device__ float g_A[Bb * Nn * Hd];     // h @ eW1[0:128] + eb1
__device__ float g_Bv[Bb * Nn * Hd];    // h @ eW1[128:256]
__device__ float g_magg[Bb * Nn * Hd];  // sum_j m_ij

__device__ __forceinline__ float silu_f(float v) {
    return v * (1.0f / (1.0f + __expf(-v)));
}

// ---------------------------------------------------------------------------
// Precompute A/Bv: one CTA per (b,n) row, 128 threads (one per output col k)
// ---------------------------------------------------------------------------
__global__ void precompute_kernel(const float* __restrict__ h,
                                  const float* __restrict__ eW1,
                                  const float* __restrict__ eb1) {
    const int row = blockIdx.x;   // b*Nn + n
    const int k = threadIdx.x;    // 0..127
    __shared__ float sh[Hd];
    sh[k] = h[row * Hd + k];
    __syncthreads();
    float a = eb1[k];
    float bv = 0.f;
#pragma unroll 8
    for (int r = 0; r < Hd; r++) {
        float hv = sh[r];
        a  += hv * eW1[r * Hd + k];
        bv += hv * eW1[(Hd + r) * Hd + k];
    }
    g_A[row * Hd + k] = a;
    g_Bv[row * Hd + k] = bv;
}

// ---------------------------------------------------------------------------
// Edge kernel: one CTA per (b,i). Fused edge MLP + coord MLP + reductions.
// ---------------------------------------------------------------------------
struct EdgeSmem {
    float W2[Hd * Hd];     // eW2
    float C1[Hd * Hd];     // cW1
    float bufA[TJ * 129];  // ping
    float bufB[TJ * 129];  // pong
    float Bv[TJ * Hd];     // Bv tile
    float Ai[Hd];
    float Wd[Hd];          // eW1 row 256 (dist weight)
    float Eb2[Hd];
    float Cb1[Hd];
    float Cw2[Hd];
    float D[TJ];           // dist_sq per row of tile
    float red[8 * Hd];     // m_agg cross-thread reduction
};

__global__ void __launch_bounds__(NT, 1)
edge_kernel(const float* __restrict__ x,
            const float* __restrict__ eW1,
            const float* __restrict__ eW2, const float* __restrict__ eb2,
            const float* __restrict__ cW1, const float* __restrict__ cb1,
            const float* __restrict__ cW2,
            float* __restrict__ xout) {
    extern __shared__ float sm_raw[];
    EdgeSmem* S = reinterpret_cast<EdgeSmem*>(sm_raw);

    const int i = blockIdx.x, b = blockIdx.y;
    const int t = threadIdx.x;
    const int tn = t & 31, tm = t >> 5;   // 32 x 8 thread grid
    const int n0 = tn * 4, m0 = tm * 4;   // 4x4 register tile per thread
    const int row_i = b * Nn + i;

    // Load weights / vectors
    for (int idx = t; idx < Hd * Hd; idx += NT) {
        S->W2[idx] = eW2[idx];
        S->C1[idx] = cW1[idx];
    }
    for (int idx = t; idx < Hd; idx += NT) {
        S->Ai[idx]  = g_A[row_i * Hd + idx];
        S->Wd[idx]  = eW1[256 * Hd + idx];
        S->Eb2[idx] = eb2[idx];
        S->Cb1[idx] = cb1[idx];
        S->Cw2[idx] = cW2[idx];
    }
    const float xi0 = x[row_i * 3 + 0];
    const float xi1 = x[row_i * 3 + 1];
    const float xi2 = x[row_i * 3 + 2];

    float magg[4] = {0.f, 0.f, 0.f, 0.f};  // per-thread partial col sums of m_ij
    float cacc0 = 0.f, cacc1 = 0.f, cacc2 = 0.f;  // coord acc (warp 0 lanes)
    __syncthreads();

    for (int jt = 0; jt < Nn / TJ; jt++) {
        const int j0 = jt * TJ;

        // Phase A: load Bv tile + dist_sq
        {
            const float* gB = &g_Bv[(b * Nn + j0) * Hd];
            for (int idx = t * 4; idx < TJ * Hd; idx += NT * 4) {
                *(float4*)&S->Bv[idx] = *(const float4*)&gB[idx];
            }
            if (t < TJ) {
                const int j = j0 + t;
                float dx = xi0 - x[(b * Nn + j) * 3 + 0];
                float dy = xi1 - x[(b * Nn + j) * 3 + 1];
                float dz = xi2 - x[(b * Nn + j) * 3 + 2];
                S->D[t] = dx * dx + dy * dy + dz * dz;
            }
        }
        __syncthreads();

        // Phase B: T1 = silu(Ai + Bv_j + d*Wd)  -> bufA
#pragma unroll
        for (int r = 0; r < 4; r++) {
            const int m = m0 + r;
            const float d = S->D[m];
#pragma unroll
            for (int c = 0; c < 4; c++) {
                const int k = n0 + c;
                float v = S->Ai[k] + S->Bv[m * Hd + k] + d * S->Wd[k];
                S->bufA[m * 129 + k] = silu_f(v);
            }
        }
        __syncthreads();

        // Phase C: bufB = silu(bufA @ W2 + eb2); accumulate m_agg
        {
            float acc[4][4];
#pragma unroll
            for (int r = 0; r < 4; r++)
#pragma unroll
                for (int c = 0; c < 4; c++) acc[r][c] = 0.f;
#pragma unroll 4
            for (int k = 0; k < Hd; k++) {
                float a0 = S->bufA[(m0 + 0) * 129 + k];
                float a1 = S->bufA[(m0 + 1) * 129 + k];
                float a2 = S->bufA[(m0 + 2) * 129 + k];
                float a3 = S->bufA[(m0 + 3) * 129 + k];
                float4 w = *(const float4*)&S->W2[k * Hd + n0];
                acc[0][0] += a0 * w.x; acc[0][1] += a0 * w.y; acc[0][2] += a0 * w.z; acc[0][3] += a0 * w.w;
                acc[1][0] += a1 * w.x; acc[1][1] += a1 * w.y; acc[1][2] += a1 * w.z; acc[1][3] += a1 * w.w;
                acc[2][0] += a2 * w.x; acc[2][1] += a2 * w.y; acc[2][2] += a2 * w.z; acc[2][3] += a2 * w.w;
                acc[3][0] += a3 * w.x; acc[3][1] += a3 * w.y; acc[3][2] += a3 * w.z; acc[3][3] += a3 * w.w;
            }
#pragma unroll
            for (int r = 0; r < 4; r++) {
#pragma unroll
                for (int c = 0; c < 4; c++) {
                    float v = silu_f(acc[r][c] + S->Eb2[n0 + c]);
                    S->bufB[(m0 + r) * 129 + n0 + c] = v;
                    magg[c] += v;
                }
            }
        }
        __syncthreads();

        // Phase D: bufA = silu(bufB @ C1 + cb1)
        {
            float acc[4][4];
#pragma unroll
            for (int r = 0; r < 4; r++)
#pragma unroll
                for (int c = 0; c < 4; c++) acc[r][c] = 0.f;
#pragma unroll 4
            for (int k = 0; k < Hd; k++) {
                float a0 = S->bufB[(m0 + 0) * 129 + k];
                float a1 = S->bufB[(m0 + 1) * 129 + k];
                float a2 = S->bufB[(m0 + 2) * 129 + k];
                float a3 = S->bufB[(m0 + 3) * 129 + k];
                float4 w = *(const float4*)&S->C1[k * Hd + n0];
                acc[0][0] += a0 * w.x; acc[0][1] += a0 * w.y; acc[0][2] += a0 * w.z; acc[0][3] += a0 * w.w;
                acc[1][0] += a1 * w.x; acc[1][1] += a1 * w.y; acc[1][2] += a1 * w.z; acc[1][3] += a1 * w.w;
                acc[2][0] += a2 * w.x; acc[2][1] += a2 * w.y; acc[2][2] += a2 * w.z; acc[2][3] += a2 * w.w;
                acc[3][0] += a3 * w.x; acc[3][1] += a3 * w.y; acc[3][2] += a3 * w.z; acc[3][3] += a3 * w.w;
            }
#pragma unroll
            for (int r = 0; r < 4; r++)
#pragma unroll
                for (int c = 0; c < 4; c++)
                    S->bufA[(m0 + r) * 129 + n0 + c] = silu_f(acc[r][c] + S->Cb1[n0 + c]);
        }
        __syncthreads();

        // Phase E: w_j = tanh(C1_row . cW2); coord accumulation (warp 0)
        if (t < TJ) {
            const int m = t;
            float dot = 0.f;
#pragma unroll 8
            for (int k = 0; k < Hd; k++) dot += S->bufA[m * 129 + k] * S->Cw2[k];
            float w = tanhf(dot);
            const int j = j0 + m;
            cacc0 += (xi0 - x[(b * Nn + j) * 3 + 0]) * w;
            cacc1 += (xi1 - x[(b * Nn + j) * 3 + 1]) * w;
            cacc2 += (xi2 - x[(b * Nn + j) * 3 + 2]) * w;
        }
        __syncthreads();
    }

    // m_agg reduction across the 8 tm groups
#pragma unroll
    for (int c = 0; c < 4; c++) S->red[tm * Hd + n0 + c] = magg[c];
    __syncthreads();
    if (t < Hd) {
        float s = 0.f;
#pragma unroll
        for (int r = 0; r < 8; r++) s += S->red[r * Hd + t];
        g_magg[row_i * Hd + t] = s;
    }

    // coord reduce across warp 0 lanes
    if (t < 32) {
#pragma unroll
        for (int off = 16; off; off >>= 1) {
            cacc0 += __shfl_down_sync(0xffffffffu, cacc0, off);
            cacc1 += __shfl_down_sync(0xffffffffu, cacc1, off);
            cacc2 += __shfl_down_sync(0xffffffffu, cacc2, off);
        }
        if (t == 0) {
            const float inv = 1.0f / (float)(Nn - 1);
            xout[row_i * 3 + 0] = xi0 + cacc0 * inv;
            xout[row_i * 3 + 1] = xi1 + cacc1 * inv;
            xout[row_i * 3 + 2] = xi2 + cacc2 * inv;
        }
    }
}

// ---------------------------------------------------------------------------
// Node MLP: h_out = h + silu([h, m_agg] @ nW1 + nb1) @ nW2 + nb2
// ---------------------------------------------------------------------------
__global__ void node_kernel(const float* __restrict__ h,
                            const float* __restrict__ nW1, const float* __restrict__ nb1,
                            const float* __restrict__ nW2, const float* __restrict__ nb2,
                            float* __restrict__ hout) {
    const int row = blockIdx.x;
    const int k = threadIdx.x;  // 0..127
    __shared__ float sin_s[2 * Hd];
    __shared__ float st1[Hd];
    sin_s[k] = h[row * Hd + k];
    sin_s[Hd + k] = g_magg[row * Hd + k];
    __syncthreads();
    float a = nb1[k];
#pragma unroll 8
    for (int r = 0; r < 2 * Hd; r++) a += sin_s[r] * nW1[r * Hd + k];
    st1[k] = silu_f(a);
    __syncthreads();
    float o = nb2[k];
#pragma unroll 8
    for (int r = 0; r < Hd; r++) o += st1[r] * nW2[r * Hd + k];
    hout[row * Hd + k] = sin_s[k] + o;
}

// ---------------------------------------------------------------------------
extern "C" void kernel_launch(void* const* d_in, const int* in_sizes, int n_in,
                              void* d_out, int out_size) {
    const float* h   = (const float*)d_in[0];
    const float* x   = (const float*)d_in[1];
    const float* eW1 = (const float*)d_in[2];
    const float* eb1 = (const float*)d_in[3];
    const float* eW2 = (const float*)d_in[4];
    const float* eb2 = (const float*)d_in[5];
    const float* nW1 = (const float*)d_in[6];
    const float* nb1 = (const float*)d_in[7];
    const float* nW2 = (const float*)d_in[8];
    const float* nb2 = (const float*)d_in[9];
    const float* cW1 = (const float*)d_in[10];
    const float* cb1 = (const float*)d_in[11];
    const float* cW2 = (const float*)d_in[12];

    float* out  = (float*)d_out;
    float* hout = out;                  // [B,N,H]
    float* xout = out + Bb * Nn * Hd;   // [B,N,3]

    precompute_kernel<<<Bb * Nn, Hd>>>(h, eW1, eb1);

    const int smem = (int)sizeof(EdgeSmem);
    cudaFuncSetAttribute(edge_kernel, cudaFuncAttributeMaxDynamicSharedMemorySize, smem);
    dim3 grid(Nn, Bb);
    edge_kernel<<<grid, NT, smem>>>(x, eW1, eW2, eb2, cW1, cb1, cW2, xout);

    node_kernel<<<Bb * Nn, Hd>>>(h, nW1, nb1, nW2, nb2, hout);
}

// round 2
// speedup vs baseline: 2.0546x; 2.0546x over previous
#include <cuda_runtime.h>
#include <cstdint>

#define Hd 128
#define Nn 512
#define Bb 2
#define TJ 64
#define NT 256
#define LDW 132   // padded row stride (floats): bank shift 4/row -> conflict-free frags

// Scratch (no allocations allowed)
__device__ float g_A[Bb * Nn * Hd];     // h @ eW1[0:128] + eb1
__device__ float g_Bv[Bb * Nn * Hd];    // h @ eW1[128:256]
__device__ float g_magg[Bb * Nn * Hd];  // sum_j m_ij

__device__ __forceinline__ float silu_f(float v) {
    return v * (1.0f / (1.0f + __expf(-v)));
}

__device__ __forceinline__ uint32_t f2tf32(float f) {
    uint32_t r;
    asm("cvt.rna.tf32.f32 %0, %1;" : "=r"(r) : "f"(f));
    return r;
}

__device__ __forceinline__ void mma_tf32(float* c,
                                         uint32_t a0, uint32_t a1, uint32_t a2, uint32_t a3,
                                         uint32_t b0, uint32_t b1) {
    asm volatile(
        "mma.sync.aligned.m16n8k8.row.col.f32.tf32.tf32.f32 "
        "{%0,%1,%2,%3},{%4,%5,%6,%7},{%8,%9},{%0,%1,%2,%3};"
        : "+f"(c[0]), "+f"(c[1]), "+f"(c[2]), "+f"(c[3])
        : "r"(a0), "r"(a1), "r"(a2), "r"(a3), "r"(b0), "r"(b1));
}

// ---------------------------------------------------------------------------
// Precompute A/Bv: one CTA per (b,n) row, 128 threads
// ---------------------------------------------------------------------------
__global__ void precompute_kernel(const float* __restrict__ h,
                                  const float* __restrict__ eW1,
                                  const float* __restrict__ eb1) {
    const int row = blockIdx.x;
    const int k = threadIdx.x;
    __shared__ float sh[Hd];
    sh[k] = h[row * Hd + k];
    __syncthreads();
    float a = eb1[k];
    float bv = 0.f;
#pragma unroll 8
    for (int r = 0; r < Hd; r++) {
        float hv = sh[r];
        a  += hv * eW1[r * Hd + k];
        bv += hv * eW1[(Hd + r) * Hd + k];
    }
    g_A[row * Hd + k] = a;
    g_Bv[row * Hd + k] = bv;
}

// ---------------------------------------------------------------------------
// Edge kernel smem
// ---------------------------------------------------------------------------
struct EdgeSmem {
    float Wt2[Hd * LDW];   // eW2 transposed [n][k], tf32 bits
    float Ct1[Hd * LDW];   // cW1 transposed [n][k], tf32 bits
    float T1[TJ * LDW];    // activations ping (tf32 bits when feeding mma)
    float T2[TJ * LDW];    // activations pong
    float Ai[Hd];
    float Wd[Hd];
    float Eb2[Hd];
    float Cb1[Hd];
    float Cw2[Hd];
    float D[TJ];
    float sx[TJ][3];
    float red[4][Hd];      // magg cross-rowblk reduction
    float wsum[8][3];      // coord cross-warp reduction
};

// One 64x128 = A[64x128] @ Wt^T, bias+silu epilogue, optional magg.
template <bool DO_MAGG, bool STORE_TF32>
__device__ __forceinline__ void gemm_tile(const float* __restrict__ A,
                                          const float* __restrict__ Wt,
                                          const float* __restrict__ bias,
                                          float* __restrict__ Out,
                                          float* macc,
                                          int lane, int rowbase, int colbase) {
    const uint32_t* Au = reinterpret_cast<const uint32_t*>(A);
    const uint32_t* Wu = reinterpret_cast<const uint32_t*>(Wt);
    const int g = lane >> 2, tig = lane & 3;

    float acc[8][4];
#pragma unroll
    for (int nt = 0; nt < 8; nt++)
#pragma unroll
        for (int c = 0; c < 4; c++) acc[nt][c] = 0.f;

    const int ra = (rowbase + g) * LDW;
    const int rb = (rowbase + g + 8) * LDW;

#pragma unroll 4
    for (int k0 = 0; k0 < Hd; k0 += 8) {
        uint32_t a0 = Au[ra + k0 + tig];
        uint32_t a1 = Au[rb + k0 + tig];
        uint32_t a2 = Au[ra + k0 + tig + 4];
        uint32_t a3 = Au[rb + k0 + tig + 4];
#pragma unroll
        for (int nt = 0; nt < 8; nt++) {
            const int n = colbase + nt * 8 + g;
            uint32_t b0 = Wu[n * LDW + k0 + tig];
            uint32_t b1 = Wu[n * LDW + k0 + tig + 4];
            mma_tf32(acc[nt], a0, a1, a2, a3, b0, b1);
        }
    }

#pragma unroll
    for (int nt = 0; nt < 8; nt++) {
        const int col = colbase + nt * 8 + 2 * tig;
        float v00 = silu_f(acc[nt][0] + bias[col]);
        float v01 = silu_f(acc[nt][1] + bias[col + 1]);
        float v10 = silu_f(acc[nt][2] + bias[col]);
        float v11 = silu_f(acc[nt][3] + bias[col + 1]);
        if (DO_MAGG) {
            macc[2 * nt]     += v00 + v10;
            macc[2 * nt + 1] += v01 + v11;
        }
        const int r0 = (rowbase + g) * LDW;
        const int r1 = (rowbase + g + 8) * LDW;
        if (STORE_TF32) {
            uint32_t* Ou = reinterpret_cast<uint32_t*>(Out);
            Ou[r0 + col]     = f2tf32(v00);
            Ou[r0 + col + 1] = f2tf32(v01);
            Ou[r1 + col]     = f2tf32(v10);
            Ou[r1 + col + 1] = f2tf32(v11);
        } else {
            Out[r0 + col]     = v00;
            Out[r0 + col + 1] = v01;
            Out[r1 + col]     = v10;
            Out[r1 + col + 1] = v11;
        }
    }
}

__global__ void __launch_bounds__(NT, 1)
edge_kernel(const float* __restrict__ x,
            const float* __restrict__ eW1,
            const float* __restrict__ eW2, const float* __restrict__ eb2,
            const float* __restrict__ cW1, const float* __restrict__ cb1,
            const float* __restrict__ cW2,
            float* __restrict__ xout) {
    extern __shared__ float sm_raw[];
    EdgeSmem* S = reinterpret_cast<EdgeSmem*>(sm_raw);

    const int i = blockIdx.x, b = blockIdx.y;
    const int t = threadIdx.x;
    const int lane = t & 31, wid = t >> 5;
    const int rowbase = (wid & 3) * 16;
    const int colbase = (wid >> 2) * 64;
    const int row_i = b * Nn + i;

    // Load weights (transposed, tf32) + vectors
    {
        uint32_t* W2u = reinterpret_cast<uint32_t*>(S->Wt2);
        uint32_t* C1u = reinterpret_cast<uint32_t*>(S->Ct1);
        for (int idx = t; idx < Hd * Hd; idx += NT) {
            const int k = idx >> 7, n = idx & 127;
            W2u[n * LDW + k] = f2tf32(eW2[idx]);
            C1u[n * LDW + k] = f2tf32(cW1[idx]);
        }
    }
    for (int idx = t; idx < Hd; idx += NT) {
        S->Ai[idx]  = g_A[row_i * Hd + idx];
        S->Wd[idx]  = eW1[256 * Hd + idx];
        S->Eb2[idx] = eb2[idx];
        S->Cb1[idx] = cb1[idx];
        S->Cw2[idx] = cW2[idx];
    }
    const float xi0 = x[row_i * 3 + 0];
    const float xi1 = x[row_i * 3 + 1];
    const float xi2 = x[row_i * 3 + 2];

    float macc[16];
#pragma unroll
    for (int c = 0; c < 16; c++) macc[c] = 0.f;
    float cacc0 = 0.f, cacc1 = 0.f, cacc2 = 0.f;
    __syncthreads();

    for (int jt = 0; jt < Nn / TJ; jt++) {
        const int j0 = jt * TJ;

        // Phase A: distances + stash x_j
        if (t < TJ) {
            const int j = j0 + t;
            float x0 = x[(b * Nn + j) * 3 + 0];
            float x1 = x[(b * Nn + j) * 3 + 1];
            float x2 = x[(b * Nn + j) * 3 + 2];
            S->sx[t][0] = x0; S->sx[t][1] = x1; S->sx[t][2] = x2;
            float dx = xi0 - x0, dy = xi1 - x1, dz = xi2 - x2;
            S->D[t] = dx * dx + dy * dy + dz * dz;
        }
        __syncthreads();

        // Phase B: T1 = tf32(silu(Ai + Bv_j + d*Wd))
        {
            const float* gB = &g_Bv[(b * Nn + j0) * Hd];
            uint32_t* T1u = reinterpret_cast<uint32_t*>(S->T1);
            for (int idx = t * 4; idx < TJ * Hd; idx += NT * 4) {
                const int m = idx >> 7, k = idx & 127;
                float4 bv = *(const float4*)&gB[idx];
                const float d = S->D[m];
                uint4 o;
                o.x = f2tf32(silu_f(S->Ai[k + 0] + bv.x + d * S->Wd[k + 0]));
                o.y = f2tf32(silu_f(S->Ai[k + 1] + bv.y + d * S->Wd[k + 1]));
                o.z = f2tf32(silu_f(S->Ai[k + 2] + bv.z + d * S->Wd[k + 2]));
                o.w = f2tf32(silu_f(S->Ai[k + 3] + bv.w + d * S->Wd[k + 3]));
                *(uint4*)&T1u[m * LDW + k] = o;
            }
        }
        __syncthreads();

        // GEMM1: T2 = silu(T1 @ eW2 + eb2), magg += colsums
        gemm_tile<true, true>(S->T1, S->Wt2, S->Eb2, S->T2, macc, lane, rowbase, colbase);
        __syncthreads();

        // GEMM2: T1 = silu(T2 @ cW1 + cb1)  (f32 output)
        gemm_tile<false, false>(S->T2, S->Ct1, S->Cb1, S->T1, nullptr, lane, rowbase, colbase);
        __syncthreads();

        // Phase E: w_j = tanh(row . cW2); coord accumulation (4 lanes per row)
        {
            const int r = t >> 2, q = t & 3;
            float dot = 0.f;
#pragma unroll 8
            for (int k = q; k < Hd; k += 4) dot += S->T1[r * LDW + k] * S->Cw2[k];
            dot += __shfl_xor_sync(0xffffffffu, dot, 1);
            dot += __shfl_xor_sync(0xffffffffu, dot, 2);
            if (q == 0) {
                float w = tanhf(dot);
                cacc0 += (xi0 - S->sx[r][0]) * w;
                cacc1 += (xi1 - S->sx[r][1]) * w;
                cacc2 += (xi2 - S->sx[r][2]) * w;
            }
        }
        __syncthreads();
    }

    // magg: reduce over groupID lanes (stride-4 groups share columns)
#pragma unroll
    for (int c = 0; c < 16; c++) {
        macc[c] += __shfl_down_sync(0xffffffffu, macc[c], 4);
        macc[c] += __shfl_down_sync(0xffffffffu, macc[c], 8);
        macc[c] += __shfl_down_sync(0xffffffffu, macc[c], 16);
    }
    if (lane < 4) {
        const int tig = lane;
#pragma unroll
        for (int nt = 0; nt < 8; nt++) {
            const int col = colbase + nt * 8 + 2 * tig;
            S->red[wid & 3][col]     = macc[2 * nt];
            S->red[wid & 3][col + 1] = macc[2 * nt + 1];
        }
    }

    // coord: full-warp reduce, then cross-warp
#pragma unroll
    for (int off = 16; off; off >>= 1) {
        cacc0 += __shfl_down_sync(0xffffffffu, cacc0, off);
        cacc1 += __shfl_down_sync(0xffffffffu, cacc1, off);
        cacc2 += __shfl_down_sync(0xffffffffu, cacc2, off);
    }
    if (lane == 0) {
        S->wsum[wid][0] = cacc0; S->wsum[wid][1] = cacc1; S->wsum[wid][2] = cacc2;
    }
    __syncthreads();

    if (t < Hd) {
        float s = S->red[0][t] + S->red[1][t] + S->red[2][t] + S->red[3][t];
        g_magg[row_i * Hd + t] = s;
    }
    if (t == 0) {
        float s0 = 0.f, s1 = 0.f, s2 = 0.f;
#pragma unroll
        for (int w = 0; w < 8; w++) { s0 += S->wsum[w][0]; s1 += S->wsum[w][1]; s2 += S->wsum[w][2]; }
        const float inv = 1.0f / (float)(Nn - 1);
        xout[row_i * 3 + 0] = xi0 + s0 * inv;
        xout[row_i * 3 + 1] = xi1 + s1 * inv;
        xout[row_i * 3 + 2] = xi2 + s2 * inv;
    }
}

// ---------------------------------------------------------------------------
// Node MLP: h_out = h + silu([h, m_agg] @ nW1 + nb1) @ nW2 + nb2
// ---------------------------------------------------------------------------
__global__ void node_kernel(const float* __restrict__ h,
                            const float* __restrict__ nW1, const float* __restrict__ nb1,
                            const float* __restrict__ nW2, const float* __restrict__ nb2,
                            float* __restrict__ hout) {
    const int row = blockIdx.x;
    const int k = threadIdx.x;
    __shared__ float sin_s[2 * Hd];
    __shared__ float st1[Hd];
    sin_s[k] = h[row * Hd + k];
    sin_s[Hd + k] = g_magg[row * Hd + k];
    __syncthreads();
    float a = nb1[k];
#pragma unroll 8
    for (int r = 0; r < 2 * Hd; r++) a += sin_s[r] * nW1[r * Hd + k];
    st1[k] = silu_f(a);
    __syncthreads();
    float o = nb2[k];
#pragma unroll 8
    for (int r = 0; r < Hd; r++) o += st1[r] * nW2[r * Hd + k];
    hout[row * Hd + k] = sin_s[k] + o;
}

// ---------------------------------------------------------------------------
extern "C" void kernel_launch(void* const* d_in, const int* in_sizes, int n_in,
                              void* d_out, int out_size) {
    const float* h   = (const float*)d_in[0];
    const float* x   = (const float*)d_in[1];
    const float* eW1 = (const float*)d_in[2];
    const float* eb1 = (const float*)d_in[3];
    const float* eW2 = (const float*)d_in[4];
    const float* eb2 = (const float*)d_in[5];
    const float* nW1 = (const float*)d_in[6];
    const float* nb1 = (const float*)d_in[7];
    const float* nW2 = (const float*)d_in[8];
    const float* nb2 = (const float*)d_in[9];
    const float* cW1 = (const float*)d_in[10];
    const float* cb1 = (const float*)d_in[11];
    const float* cW2 = (const float*)d_in[12];

    float* out  = (float*)d_out;
    float* hout = out;
    float* xout = out + Bb * Nn * Hd;

    precompute_kernel<<<Bb * Nn, Hd>>>(h, eW1, eb1);

    const int smem = (int)sizeof(EdgeSmem);
    static int configured = 0;
    cudaFuncSetAttribute(edge_kernel, cudaFuncAttributeMaxDynamicSharedMemorySize, smem);
    (void)configured;
    dim3 grid(Nn, Bb);
    edge_kernel<<<grid, NT, smem>>>(x, eW1, eW2, eb2, cW1, cb1, cW2, xout);

    node_kernel<<<Bb * Nn, Hd>>>(h, nW1, nb1, nW2, nb2, hout);
}

// round 5
// speedup vs baseline: 6.8972x; 3.3570x over previous
#include <cuda_runtime.h>
#include <cuda_fp16.h>
#include <cstdint>

#define Hd 128
#define Nn 512
#define Bb 2
#define TJ 64
#define NT 256
#define LDK 136     // padded row stride in halfs: row shift = 4 banks -> conflict-free
#define NTILES (Nn / TJ)

// ---------------- device scratch (no allocations allowed) ------------------
__device__ float g_A[Bb * Nn * Hd];      // h @ eW1[0:128] + eb1
__device__ float g_Bv[Bb * Nn * Hd];     // h @ eW1[128:256]
__device__ float g_magg[Bb * Nn * Hd];   // sum_j m_ij
__device__ uint4 g_W2h[2176];            // eW2^T f16 [n][k] pad LDK  (34816 B)
__device__ uint4 g_C1h[2176];            // cW1^T f16 [n][k] pad LDK

__device__ __forceinline__ float silu_f(float v) {
    return __fdividef(v, 1.0f + __expf(-v));
}
__device__ __forceinline__ uint32_t pk2(float a, float b) {
    __half2 h = __floats2half2_rn(a, b);
    return *reinterpret_cast<uint32_t*>(&h);
}
__device__ __forceinline__ void mma16816(float* c,
                                         uint32_t a0, uint32_t a1, uint32_t a2, uint32_t a3,
                                         uint32_t b0, uint32_t b1) {
    asm volatile(
        "mma.sync.aligned.m16n8k16.row.col.f32.f16.f16.f32 "
        "{%0,%1,%2,%3},{%4,%5,%6,%7},{%8,%9},{%0,%1,%2,%3};"
        : "+f"(c[0]), "+f"(c[1]), "+f"(c[2]), "+f"(c[3])
        : "r"(a0), "r"(a1), "r"(a2), "r"(a3), "r"(b0), "r"(b1));
}

// ---------------------------------------------------------------------------
// Weight conversion: W[k][n] f32 -> Wt[n][k] f16 padded (done once, tiny)
// ---------------------------------------------------------------------------
__global__ void convert_w_kernel(const float* __restrict__ eW2,
                                 const float* __restrict__ cW1) {
    int idx = blockIdx.x * blockDim.x + threadIdx.x;  // k*128+n
    if (idx >= Hd * Hd) return;
    int k = idx >> 7, n = idx & 127;
    ((__half*)g_W2h)[n * LDK + k] = __float2half(eW2[idx]);
    ((__half*)g_C1h)[n * LDK + k] = __float2half(cW1[idx]);
}

// dummies: position edge_kernel as the 6th launch for ncu (-s 5 -c 1)
__global__ void dummy_kernel() {}

// ---------------------------------------------------------------------------
// Precompute A/Bv: one CTA per (b,n) row, 128 threads (validated R1/R2)
// ---------------------------------------------------------------------------
__global__ void precompute_kernel(const float* __restrict__ h,
                                  const float* __restrict__ eW1,
                                  const float* __restrict__ eb1) {
    const int row = blockIdx.x;
    const int k = threadIdx.x;
    __shared__ float sh[Hd];
    sh[k] = h[row * Hd + k];
    __syncthreads();
    float a = eb1[k];
    float bv = 0.f;
#pragma unroll 8
    for (int r = 0; r < Hd; r++) {
        float hv = sh[r];
        a  += hv * eW1[r * Hd + k];
        bv += hv * eW1[(Hd + r) * Hd + k];
    }
    g_A[row * Hd + k] = a;
    g_Bv[row * Hd + k] = bv;
}

// ---------------------------------------------------------------------------
// Edge kernel: 1 CTA per (b,i), f16 HMMA, occ-2 layout (~110KB smem)
// ---------------------------------------------------------------------------
struct __align__(16) ESmem {
    __half W2[Hd * LDK];   // eW2^T
    __half C1[Hd * LDK];   // cW1^T
    __half T1[TJ * LDK];   // silu(edge-lin1) tile
    __half T2[TJ * LDK];   // m_ij tile
    float sAi[Hd], sWd[Hd], sEb2[Hd], sCb1[Hd], sCw2[Hd];
    float SD[TJ];
    float sx3[TJ * 3];
    float P[2][TJ];
    float mred[4][Hd];
    float csum[2][3];
};

// k-loop: acc[8][4] += A[16x128] @ W^T[cols colbase..+64]
__device__ __forceinline__ void gemm_acc(const __half* __restrict__ A,
                                         const __half* __restrict__ W,
                                         float acc[8][4],
                                         int g, int tig, int rowbase, int colbase) {
    const uint32_t* Au = reinterpret_cast<const uint32_t*>(A);
    const uint32_t* Wu = reinterpret_cast<const uint32_t*>(W);
    const int ra = (rowbase + g) * (LDK / 2);
    const int rb = (rowbase + g + 8) * (LDK / 2);
#pragma unroll
    for (int ks = 0; ks < 8; ks++) {
        const int kh = ks * 8;  // k0/2
        uint32_t a0 = Au[ra + kh + tig];
        uint32_t a1 = Au[rb + kh + tig];
        uint32_t a2 = Au[ra + kh + 4 + tig];
        uint32_t a3 = Au[rb + kh + 4 + tig];
#pragma unroll
        for (int nt = 0; nt < 8; nt++) {
            const int n = colbase + nt * 8 + g;
            const int wb = n * (LDK / 2) + kh;
            uint32_t b0 = Wu[wb + tig];
            uint32_t b1 = Wu[wb + 4 + tig];
            mma16816(acc[nt], a0, a1, a2, a3, b0, b1);
        }
    }
}

__global__ void __launch_bounds__(NT, 2)
edge_kernel(const float* __restrict__ x,
            const float* __restrict__ eW1,
            const float* __restrict__ eb2, const float* __restrict__ cb1,
            const float* __restrict__ cW2,
            float* __restrict__ xout) {
    extern __shared__ __align__(16) unsigned char sm_raw[];
    ESmem* S = reinterpret_cast<ESmem*>(sm_raw);

    const int i = blockIdx.x, b = blockIdx.y;
    const int t = threadIdx.x;
    const int lane = t & 31, wid = t >> 5;
    const int g = lane >> 2, tig = lane & 3;
    const int rowbase = (wid & 3) * 16;
    const int colbase = (wid >> 2) * 64;
    const int row_i = b * Nn + i;

    // weights: flat copies from pre-converted global
    {
        uint4* dw = (uint4*)S->W2;
        uint4* dc = (uint4*)S->C1;
        for (int idx = t; idx < 2176; idx += NT) {
            dw[idx] = g_W2h[idx];
            dc[idx] = g_C1h[idx];
        }
    }
    for (int idx = t; idx < Hd; idx += NT) {
        S->sAi[idx]  = g_A[row_i * Hd + idx];
        S->sWd[idx]  = eW1[256 * Hd + idx];
        S->sEb2[idx] = eb2[idx];
        S->sCb1[idx] = cb1[idx];
        S->sCw2[idx] = cW2[idx];
    }
    const float xi0 = x[row_i * 3 + 0];
    const float xi1 = x[row_i * 3 + 1];
    const float xi2 = x[row_i * 3 + 2];

    float macc[16];
#pragma unroll
    for (int c = 0; c < 16; c++) macc[c] = 0.f;
    float cx = 0.f, cy = 0.f, cz = 0.f;
    __syncthreads();

    for (int jt = 0; jt < NTILES; jt++) {
        const int j0 = jt * TJ;

        // Phase A: distances + x_j
        if (t < TJ) {
            const int j = j0 + t;
            float x0 = x[(b * Nn + j) * 3 + 0];
            float x1 = x[(b * Nn + j) * 3 + 1];
            float x2 = x[(b * Nn + j) * 3 + 2];
            S->sx3[t * 3 + 0] = x0; S->sx3[t * 3 + 1] = x1; S->sx3[t * 3 + 2] = x2;
            float dx = xi0 - x0, dy = xi1 - x1, dz = xi2 - x2;
            S->SD[t] = dx * dx + dy * dy + dz * dz;
        }
        __syncthreads();

        // Phase B: T1 = f16(silu(Ai + Bv_j + d*Wd))
#pragma unroll
        for (int it = 0; it < 8; it++) {
            const int idx = t * 4 + it * NT * 4;    // 4 floats per step
            const int m = idx >> 7, k = idx & 127;
            float4 bv = *(const float4*)&g_Bv[(size_t)(b * Nn + j0 + m) * Hd + k];
            const float d = S->SD[m];
            float v0 = silu_f(S->sAi[k + 0] + bv.x + d * S->sWd[k + 0]);
            float v1 = silu_f(S->sAi[k + 1] + bv.y + d * S->sWd[k + 1]);
            float v2 = silu_f(S->sAi[k + 2] + bv.z + d * S->sWd[k + 2]);
            float v3 = silu_f(S->sAi[k + 3] + bv.w + d * S->sWd[k + 3]);
            uint2 pk; pk.x = pk2(v0, v1); pk.y = pk2(v2, v3);
            *(uint2*)&S->T1[m * LDK + k] = pk;
        }
        __syncthreads();

        // GEMM1 + epilogue: T2 = f16(silu(T1 @ eW2 + eb2)), magg += colsum
        {
            float acc[8][4];
#pragma unroll
            for (int nt = 0; nt < 8; nt++)
#pragma unroll
                for (int c = 0; c < 4; c++) acc[nt][c] = 0.f;
            gemm_acc(S->T1, S->W2, acc, g, tig, rowbase, colbase);
#pragma unroll
            for (int nt = 0; nt < 8; nt++) {
                const int col = colbase + nt * 8 + 2 * tig;
                float v00 = silu_f(acc[nt][0] + S->sEb2[col]);
                float v01 = silu_f(acc[nt][1] + S->sEb2[col + 1]);
                float v10 = silu_f(acc[nt][2] + S->sEb2[col]);
                float v11 = silu_f(acc[nt][3] + S->sEb2[col + 1]);
                *(uint32_t*)&S->T2[(rowbase + g) * LDK + col]     = pk2(v00, v01);
                *(uint32_t*)&S->T2[(rowbase + g + 8) * LDK + col] = pk2(v10, v11);
                macc[2 * nt]     += v00 + v10;
                macc[2 * nt + 1] += v01 + v11;
            }
        }
        __syncthreads();

        // GEMM2 + fused dot epilogue: P = dot(silu(T2 @ cW1 + cb1), cW2)
        {
            float acc[8][4];
#pragma unroll
            for (int nt = 0; nt < 8; nt++)
#pragma unroll
                for (int c = 0; c < 4; c++) acc[nt][c] = 0.f;
            gemm_acc(S->T2, S->C1, acc, g, tig, rowbase, colbase);
            float dotA = 0.f, dotB = 0.f;
#pragma unroll
            for (int nt = 0; nt < 8; nt++) {
                const int col = colbase + nt * 8 + 2 * tig;
                const float w0 = S->sCw2[col], w1 = S->sCw2[col + 1];
                const float b0 = S->sCb1[col], b1 = S->sCb1[col + 1];
                dotA += silu_f(acc[nt][0] + b0) * w0 + silu_f(acc[nt][1] + b1) * w1;
                dotB += silu_f(acc[nt][2] + b0) * w0 + silu_f(acc[nt][3] + b1) * w1;
            }
            dotA += __shfl_xor_sync(0xffffffffu, dotA, 1);
            dotA += __shfl_xor_sync(0xffffffffu, dotA, 2);
            dotB += __shfl_xor_sync(0xffffffffu, dotB, 1);
            dotB += __shfl_xor_sync(0xffffffffu, dotB, 2);
            if (tig == 0) {
                S->P[wid >> 2][rowbase + g]     = dotA;
                S->P[wid >> 2][rowbase + g + 8] = dotB;
            }
        }
        __syncthreads();

        // coord accumulation
        if (t < TJ) {
            float wv = tanhf(S->P[0][t] + S->P[1][t]);
            cx += (xi0 - S->sx3[t * 3 + 0]) * wv;
            cy += (xi1 - S->sx3[t * 3 + 1]) * wv;
            cz += (xi2 - S->sx3[t * 3 + 2]) * wv;
        }
        __syncthreads();
    }

    // magg: reduce group-lanes (stride 4/8/16 share columns), store per rowblk
#pragma unroll
    for (int c = 0; c < 16; c++) {
        macc[c] += __shfl_down_sync(0xffffffffu, macc[c], 4);
        macc[c] += __shfl_down_sync(0xffffffffu, macc[c], 8);
        macc[c] += __shfl_down_sync(0xffffffffu, macc[c], 16);
    }
    if (lane < 4) {
#pragma unroll
        for (int nt = 0; nt < 8; nt++) {
            const int col = colbase + nt * 8 + 2 * lane;
            S->mred[wid & 3][col]     = macc[2 * nt];
            S->mred[wid & 3][col + 1] = macc[2 * nt + 1];
        }
    }

    // coord cross-warp reduce (warps 0,1 hold partials)
    if (t < TJ) {
#pragma unroll
        for (int off = 16; off; off >>= 1) {
            cx += __shfl_down_sync(0xffffffffu, cx, off);
            cy += __shfl_down_sync(0xffffffffu, cy, off);
            cz += __shfl_down_sync(0xffffffffu, cz, off);
        }
        if (lane == 0) { S->csum[wid][0] = cx; S->csum[wid][1] = cy; S->csum[wid][2] = cz; }
    }
    __syncthreads();

    if (t < Hd) {
        float s = S->mred[0][t] + S->mred[1][t] + S->mred[2][t] + S->mred[3][t];
        g_magg[row_i * Hd + t] = s;
    }
    if (t == 0) {
        const float inv = 1.0f / (float)(Nn - 1);
        xout[row_i * 3 + 0] = xi0 + (S->csum[0][0] + S->csum[1][0]) * inv;
        xout[row_i * 3 + 1] = xi1 + (S->csum[0][1] + S->csum[1][1]) * inv;
        xout[row_i * 3 + 2] = xi2 + (S->csum[0][2] + S->csum[1][2]) * inv;
    }
}

// ---------------------------------------------------------------------------
// Node MLP: h_out = h + silu([h, m_agg] @ nW1 + nb1) @ nW2 + nb2
// ---------------------------------------------------------------------------
__global__ void node_kernel(const float* __restrict__ h,
                            const float* __restrict__ nW1, const float* __restrict__ nb1,
                            const float* __restrict__ nW2, const float* __restrict__ nb2,
                            float* __restrict__ hout) {
    const int row = blockIdx.x;
    const int k = threadIdx.x;
    __shared__ float sin_s[2 * Hd];
    __shared__ float st1[Hd];
    sin_s[k] = h[row * Hd + k];
    sin_s[Hd + k] = g_magg[row * Hd + k];
    __syncthreads();
    float a = nb1[k];
#pragma unroll 8
    for (int r = 0; r < 2 * Hd; r++) a += sin_s[r] * nW1[r * Hd + k];
    st1[k] = silu_f(a);
    __syncthreads();
    float o = nb2[k];
#pragma unroll 8
    for (int r = 0; r < Hd; r++) o += st1[r] * nW2[r * Hd + k];
    hout[row * Hd + k] = sin_s[k] + o;
}

// ---------------------------------------------------------------------------
extern "C" void kernel_launch(void* const* d_in, const int* in_sizes, int n_in,
                              void* d_out, int out_size) {
    const float* h   = (const float*)d_in[0];
    const float* x   = (const float*)d_in[1];
    const float* eW1 = (const float*)d_in[2];
    const float* eb1 = (const float*)d_in[3];
    const float* eW2 = (const float*)d_in[4];
    const float* eb2 = (const float*)d_in[5];
    const float* nW1 = (const float*)d_in[6];
    const float* nb1 = (const float*)d_in[7];
    const float* nW2 = (const float*)d_in[8];
    const float* nb2 = (const float*)d_in[9];
    const float* cW1 = (const float*)d_in[10];
    const float* cb1 = (const float*)d_in[11];
    const float* cW2 = (const float*)d_in[12];

    float* out  = (float*)d_out;
    float* hout = out;
    float* xout = out + Bb * Nn * Hd;

    convert_w_kernel<<<64, 256>>>(eW2, cW1);          // launch 1
    precompute_kernel<<<Bb * Nn, Hd>>>(h, eW1, eb1);  // launch 2
    dummy_kernel<<<1, 32>>>();                        // launch 3
    dummy_kernel<<<1, 32>>>();                        // launch 4
    dummy_kernel<<<1, 32>>>();                        // launch 5

    const int smem = (int)sizeof(ESmem);
    cudaFuncSetAttribute(edge_kernel, cudaFuncAttributeMaxDynamicSharedMemorySize, smem);
    dim3 grid(Nn, Bb);
    edge_kernel<<<grid, NT, smem>>>(x, eW1, eb2, cb1, cW2, xout);  // launch 6 (ncu)

    node_kernel<<<Bb * Nn, Hd>>>(h, nW1, nb1, nW2, nb2, hout);     // launch 7
}

// round 6
// speedup vs baseline: 7.5479x; 1.0943x over previous
#include <cuda_runtime.h>
#include <cuda_fp16.h>
#include <cstdint>

#define Hd 128
#define Nn 512
#define Bb 2
#define TJ 128
#define NT 256
#define LDK 136     // padded row stride in halfs: 68 words -> 4-bank shift/row, conflict-free
#define NTILES (Nn / TJ)

// ---------------- device scratch (no allocations allowed) ------------------
__device__ float g_A[Bb * Nn * Hd];      // h @ eW1[0:128] + eb1
__device__ float g_Bv[Bb * Nn * Hd];     // h @ eW1[128:256]
__device__ float g_magg[Bb * Nn * Hd];   // sum_j m_ij
__device__ uint4 g_W2h[2176];            // eW2^T f16 [n][k] pad LDK
__device__ uint4 g_C1h[2176];            // cW1^T f16 [n][k] pad LDK

__device__ __forceinline__ float tanh_f(float x) {
    float r;
    asm("tanh.approx.f32 %0, %1;" : "=f"(r) : "f"(x));
    return r;
}
// silu(x) = x * sigmoid(x) = 0.5x * (1 + tanh(x/2))  -> single MUFU
__device__ __forceinline__ float silu_f(float v) {
    float h = 0.5f * v;
    return fmaf(h, tanh_f(h), h);
}
__device__ __forceinline__ uint32_t pk2(float a, float b) {
    __half2 h = __floats2half2_rn(a, b);
    return *reinterpret_cast<uint32_t*>(&h);
}
__device__ __forceinline__ void mma16816(float* c,
                                         uint32_t a0, uint32_t a1, uint32_t a2, uint32_t a3,
                                         uint32_t b0, uint32_t b1) {
    asm volatile(
        "mma.sync.aligned.m16n8k16.row.col.f32.f16.f16.f32 "
        "{%0,%1,%2,%3},{%4,%5,%6,%7},{%8,%9},{%0,%1,%2,%3};"
        : "+f"(c[0]), "+f"(c[1]), "+f"(c[2]), "+f"(c[3])
        : "r"(a0), "r"(a1), "r"(a2), "r"(a3), "r"(b0), "r"(b1));
}

// ---------------------------------------------------------------------------
// Weight conversion: W[k][n] f32 -> Wt[n][k] f16 padded (once, tiny)
// ---------------------------------------------------------------------------
__global__ void convert_w_kernel(const float* __restrict__ eW2,
                                 const float* __restrict__ cW1) {
    int idx = blockIdx.x * blockDim.x + threadIdx.x;  // k*128+n
    if (idx >= Hd * Hd) return;
    int k = idx >> 7, n = idx & 127;
    ((__half*)g_W2h)[n * LDK + k] = __float2half(eW2[idx]);
    ((__half*)g_C1h)[n * LDK + k] = __float2half(cW1[idx]);
}

// ---------------------------------------------------------------------------
// Precompute A/Bv: 16 rows per CTA, 256 threads (k = t&127, sel = t>>7)
// ---------------------------------------------------------------------------
__global__ void precompute_kernel(const float* __restrict__ h,
                                  const float* __restrict__ eW1,
                                  const float* __restrict__ eb1) {
    __shared__ float sh[16][Hd];
    const int row0 = blockIdx.x * 16;
    const int t = threadIdx.x, k = t & 127, sel = t >> 7;
    for (int idx = t; idx < 16 * Hd; idx += NT)
        sh[idx >> 7][idx & 127] = h[row0 * Hd + idx];
    __syncthreads();
    float acc[16];
#pragma unroll
    for (int i = 0; i < 16; i++) acc[i] = sel ? 0.f : eb1[k];
    const float* w = eW1 + sel * Hd * Hd + k;
#pragma unroll 4
    for (int r = 0; r < Hd; r++) {
        float wv = w[r * Hd];
#pragma unroll
        for (int i = 0; i < 16; i++) acc[i] += sh[i][r] * wv;
    }
    float* dst = sel ? g_Bv : g_A;
#pragma unroll
    for (int i = 0; i < 16; i++) dst[(row0 + i) * Hd + k] = acc[i];
}

// ---------------------------------------------------------------------------
// Edge kernel: 1 CTA per (b,i); TJ=128; warp tile 32 rows x 64 cols; occ 1
// ---------------------------------------------------------------------------
struct __align__(16) ESmem {
    __half W2[Hd * LDK];   // eW2^T
    __half C1[Hd * LDK];   // cW1^T
    __half T1[TJ * LDK];   // silu(edge-lin1) tile
    __half T2[TJ * LDK];   // m_ij tile
    float sAi[Hd], sWd[Hd], sEb2[Hd], sCb1[Hd], sCw2[Hd];
    float SD[TJ];
    float sx3[TJ * 3];
    float P[2][TJ];
    float mred[4][Hd];
    float csum[4][3];
};

// acc[0..7]: rowblock 0 (rows rowbase..+15), acc[8..15]: rowblock 1 (+16..31)
__device__ __forceinline__ void gemm_acc(const __half* __restrict__ A,
                                         const __half* __restrict__ W,
                                         float acc[16][4],
                                         int g, int tig, int rowbase, int colbase) {
    const uint32_t* Au = reinterpret_cast<const uint32_t*>(A);
    const uint32_t* Wu = reinterpret_cast<const uint32_t*>(W);
    const int r00 = (rowbase + g) * (LDK / 2);
    const int r01 = (rowbase + g + 8) * (LDK / 2);
    const int r10 = (rowbase + 16 + g) * (LDK / 2);
    const int r11 = (rowbase + 24 + g) * (LDK / 2);
#pragma unroll
    for (int ks = 0; ks < 8; ks++) {
        const int kh = ks * 8;  // half2 units: 16 halfs per k-step
        uint32_t a00 = Au[r00 + kh + tig];
        uint32_t a01 = Au[r01 + kh + tig];
        uint32_t a02 = Au[r00 + kh + 4 + tig];
        uint32_t a03 = Au[r01 + kh + 4 + tig];
        uint32_t a10 = Au[r10 + kh + tig];
        uint32_t a11 = Au[r11 + kh + tig];
        uint32_t a12 = Au[r10 + kh + 4 + tig];
        uint32_t a13 = Au[r11 + kh + 4 + tig];
#pragma unroll
        for (int nb = 0; nb < 8; nb++) {
            const int n = colbase + nb * 8 + g;
            const int wb = n * (LDK / 2) + kh;
            uint32_t b0 = Wu[wb + tig];
            uint32_t b1 = Wu[wb + 4 + tig];
            mma16816(acc[nb],     a00, a01, a02, a03, b0, b1);
            mma16816(acc[8 + nb], a10, a11, a12, a13, b0, b1);
        }
    }
}

__global__ void __launch_bounds__(NT, 1)
edge_kernel(const float* __restrict__ x,
            const float* __restrict__ eW1,
            const float* __restrict__ eb2, const float* __restrict__ cb1,
            const float* __restrict__ cW2,
            float* __restrict__ xout) {
    extern __shared__ __align__(16) unsigned char sm_raw[];
    ESmem* S = reinterpret_cast<ESmem*>(sm_raw);

    const int i = blockIdx.x, b = blockIdx.y;
    const int t = threadIdx.x;
    const int lane = t & 31, wid = t >> 5;
    const int g = lane >> 2, tig = lane & 3;
    const int rowbase = (wid & 3) * 32;   // 4 rowgroups of 32 rows
    const int colbase = (wid >> 2) * 64;  // 2 colgroups of 64 cols
    const int cg = wid >> 2;
    const int row_i = b * Nn + i;

    // weights: flat copies from pre-converted global
    {
        uint4* dw = (uint4*)S->W2;
        uint4* dc = (uint4*)S->C1;
        for (int idx = t; idx < 2176; idx += NT) {
            dw[idx] = g_W2h[idx];
            dc[idx] = g_C1h[idx];
        }
    }
    for (int idx = t; idx < Hd; idx += NT) {
        S->sAi[idx]  = g_A[row_i * Hd + idx];
        S->sWd[idx]  = eW1[256 * Hd + idx];
        S->sEb2[idx] = eb2[idx];
        S->sCb1[idx] = cb1[idx];
        S->sCw2[idx] = cW2[idx];
    }
    const float xi0 = x[row_i * 3 + 0];
    const float xi1 = x[row_i * 3 + 1];
    const float xi2 = x[row_i * 3 + 2];

    float macc[16];
#pragma unroll
    for (int c = 0; c < 16; c++) macc[c] = 0.f;
    float cx = 0.f, cy = 0.f, cz = 0.f;
    __syncthreads();

    for (int jt = 0; jt < NTILES; jt++) {
        const int j0 = jt * TJ;

        // Phase A: distances + x_j
        if (t < TJ) {
            const int j = j0 + t;
            float x0 = x[(b * Nn + j) * 3 + 0];
            float x1 = x[(b * Nn + j) * 3 + 1];
            float x2 = x[(b * Nn + j) * 3 + 2];
            S->sx3[t * 3 + 0] = x0; S->sx3[t * 3 + 1] = x1; S->sx3[t * 3 + 2] = x2;
            float dx = xi0 - x0, dy = xi1 - x1, dz = xi2 - x2;
            S->SD[t] = dx * dx + dy * dy + dz * dz;
        }
        __syncthreads();

        // Phase B: T1 = f16(silu(Ai + Bv_j + d*Wd)), 128x128
#pragma unroll
        for (int it = 0; it < 16; it++) {
            const int idx = t * 4 + it * NT * 4;
            const int m = idx >> 7, k = idx & 127;
            float4 bv = *(const float4*)&g_Bv[(size_t)(b * Nn + j0 + m) * Hd + k];
            const float d = S->SD[m];
            float v0 = silu_f(S->sAi[k + 0] + bv.x + d * S->sWd[k + 0]);
            float v1 = silu_f(S->sAi[k + 1] + bv.y + d * S->sWd[k + 1]);
            float v2 = silu_f(S->sAi[k + 2] + bv.z + d * S->sWd[k + 2]);
            float v3 = silu_f(S->sAi[k + 3] + bv.w + d * S->sWd[k + 3]);
            uint2 pk; pk.x = pk2(v0, v1); pk.y = pk2(v2, v3);
            *(uint2*)&S->T1[m * LDK + k] = pk;
        }
        __syncthreads();

        // GEMM1 + epilogue: T2 = f16(silu(T1 @ eW2 + eb2)), magg += colsums
        {
            float acc[16][4];
#pragma unroll
            for (int q = 0; q < 16; q++)
#pragma unroll
                for (int c = 0; c < 4; c++) acc[q][c] = 0.f;
            gemm_acc(S->T1, S->W2, acc, g, tig, rowbase, colbase);
            const int r0 = rowbase + g, r1 = r0 + 8, r2 = r0 + 16, r3 = r0 + 24;
#pragma unroll
            for (int nb = 0; nb < 8; nb++) {
                const int col = colbase + nb * 8 + 2 * tig;
                const float bb0 = S->sEb2[col], bb1 = S->sEb2[col + 1];
                float v00 = silu_f(acc[nb][0] + bb0);
                float v01 = silu_f(acc[nb][1] + bb1);
                float v10 = silu_f(acc[nb][2] + bb0);
                float v11 = silu_f(acc[nb][3] + bb1);
                float v20 = silu_f(acc[8 + nb][0] + bb0);
                float v21 = silu_f(acc[8 + nb][1] + bb1);
                float v30 = silu_f(acc[8 + nb][2] + bb0);
                float v31 = silu_f(acc[8 + nb][3] + bb1);
                *(uint32_t*)&S->T2[r0 * LDK + col] = pk2(v00, v01);
                *(uint32_t*)&S->T2[r1 * LDK + col] = pk2(v10, v11);
                *(uint32_t*)&S->T2[r2 * LDK + col] = pk2(v20, v21);
                *(uint32_t*)&S->T2[r3 * LDK + col] = pk2(v30, v31);
                macc[2 * nb]     += v00 + v10 + v20 + v30;
                macc[2 * nb + 1] += v01 + v11 + v21 + v31;
            }
        }
        __syncthreads();

        // GEMM2 + fused dot: P[cg][row] = dot(silu(T2 @ cW1 + cb1), cW2)
        {
            float acc[16][4];
#pragma unroll
            for (int q = 0; q < 16; q++)
#pragma unroll
                for (int c = 0; c < 4; c++) acc[q][c] = 0.f;
            gemm_acc(S->T2, S->C1, acc, g, tig, rowbase, colbase);
            float d0 = 0.f, d1 = 0.f, d2 = 0.f, d3 = 0.f;
#pragma unroll
            for (int nb = 0; nb < 8; nb++) {
                const int col = colbase + nb * 8 + 2 * tig;
                const float w0 = S->sCw2[col], w1 = S->sCw2[col + 1];
                const float bb0 = S->sCb1[col], bb1 = S->sCb1[col + 1];
                d0 += silu_f(acc[nb][0] + bb0) * w0 + silu_f(acc[nb][1] + bb1) * w1;
                d1 += silu_f(acc[nb][2] + bb0) * w0 + silu_f(acc[nb][3] + bb1) * w1;
                d2 += silu_f(acc[8 + nb][0] + bb0) * w0 + silu_f(acc[8 + nb][1] + bb1) * w1;
                d3 += silu_f(acc[8 + nb][2] + bb0) * w0 + silu_f(acc[8 + nb][3] + bb1) * w1;
            }
            d0 += __shfl_xor_sync(0xffffffffu, d0, 1); d0 += __shfl_xor_sync(0xffffffffu, d0, 2);
            d1 += __shfl_xor_sync(0xffffffffu, d1, 1); d1 += __shfl_xor_sync(0xffffffffu, d1, 2);
            d2 += __shfl_xor_sync(0xffffffffu, d2, 1); d2 += __shfl_xor_sync(0xffffffffu, d2, 2);
            d3 += __shfl_xor_sync(0xffffffffu, d3, 1); d3 += __shfl_xor_sync(0xffffffffu, d3, 2);
            if (tig == 0) {
                S->P[cg][rowbase + g]      = d0;
                S->P[cg][rowbase + g + 8]  = d1;
                S->P[cg][rowbase + g + 16] = d2;
                S->P[cg][rowbase + g + 24] = d3;
            }
        }
        __syncthreads();

        // coord accumulation over this tile
        if (t < TJ) {
            float wv = tanh_f(S->P[0][t] + S->P[1][t]);
            cx += (xi0 - S->sx3[t * 3 + 0]) * wv;
            cy += (xi1 - S->sx3[t * 3 + 1]) * wv;
            cz += (xi2 - S->sx3[t * 3 + 2]) * wv;
        }
        __syncthreads();
    }

    // magg: reduce lanes sharing columns (g varies, tig fixed), store per rowgroup
#pragma unroll
    for (int c = 0; c < 16; c++) {
        macc[c] += __shfl_down_sync(0xffffffffu, macc[c], 4);
        macc[c] += __shfl_down_sync(0xffffffffu, macc[c], 8);
        macc[c] += __shfl_down_sync(0xffffffffu, macc[c], 16);
    }
    if (lane < 4) {
#pragma unroll
        for (int nb = 0; nb < 8; nb++) {
            const int col = colbase + nb * 8 + 2 * lane;
            S->mred[wid & 3][col]     = macc[2 * nb];
            S->mred[wid & 3][col + 1] = macc[2 * nb + 1];
        }
    }

    // coord cross-warp reduce (warps 0-3 hold partials for rows 0..127)
    if (t < TJ) {
#pragma unroll
        for (int off = 16; off; off >>= 1) {
            cx += __shfl_down_sync(0xffffffffu, cx, off);
            cy += __shfl_down_sync(0xffffffffu, cy, off);
            cz += __shfl_down_sync(0xffffffffu, cz, off);
        }
        if (lane == 0) { S->csum[wid][0] = cx; S->csum[wid][1] = cy; S->csum[wid][2] = cz; }
    }
    __syncthreads();

    if (t < Hd) {
        float s = S->mred[0][t] + S->mred[1][t] + S->mred[2][t] + S->mred[3][t];
        g_magg[row_i * Hd + t] = s;
    }
    if (t == 0) {
        const float inv = 1.0f / (float)(Nn - 1);
        float s0 = S->csum[0][0] + S->csum[1][0] + S->csum[2][0] + S->csum[3][0];
        float s1 = S->csum[0][1] + S->csum[1][1] + S->csum[2][1] + S->csum[3][1];
        float s2 = S->csum[0][2] + S->csum[1][2] + S->csum[2][2] + S->csum[3][2];
        xout[row_i * 3 + 0] = xi0 + s0 * inv;
        xout[row_i * 3 + 1] = xi1 + s1 * inv;
        xout[row_i * 3 + 2] = xi2 + s2 * inv;
    }
}

// ---------------------------------------------------------------------------
// Node MLP: h_out = h + silu([h, m_agg] @ nW1 + nb1) @ nW2 + nb2
// ---------------------------------------------------------------------------
__global__ void node_kernel(const float* __restrict__ h,
                            const float* __restrict__ nW1, const float* __restrict__ nb1,
                            const float* __restrict__ nW2, const float* __restrict__ nb2,
                            float* __restrict__ hout) {
    const int row = blockIdx.x;
    const int k = threadIdx.x;
    __shared__ float sin_s[2 * Hd];
    __shared__ float st1[Hd];
    sin_s[k] = h[row * Hd + k];
    sin_s[Hd + k] = g_magg[row * Hd + k];
    __syncthreads();
    float a = nb1[k];
#pragma unroll 8
    for (int r = 0; r < 2 * Hd; r++) a += sin_s[r] * nW1[r * Hd + k];
    st1[k] = silu_f(a);
    __syncthreads();
    float o = nb2[k];
#pragma unroll 8
    for (int r = 0; r < Hd; r++) o += st1[r] * nW2[r * Hd + k];
    hout[row * Hd + k] = sin_s[k] + o;
}

// ---------------------------------------------------------------------------
extern "C" void kernel_launch(void* const* d_in, const int* in_sizes, int n_in,
                              void* d_out, int out_size) {
    const float* h   = (const float*)d_in[0];
    const float* x   = (const float*)d_in[1];
    const float* eW1 = (const float*)d_in[2];
    const float* eb1 = (const float*)d_in[3];
    const float* eW2 = (const float*)d_in[4];
    const float* eb2 = (const float*)d_in[5];
    const float* nW1 = (const float*)d_in[6];
    const float* nb1 = (const float*)d_in[7];
    const float* nW2 = (const float*)d_in[8];
    const float* nb2 = (const float*)d_in[9];
    const float* cW1 = (const float*)d_in[10];
    const float* cb1 = (const float*)d_in[11];
    const float* cW2 = (const float*)d_in[12];

    float* out  = (float*)d_out;
    float* hout = out;
    float* xout = out + Bb * Nn * Hd;

    convert_w_kernel<<<64, 256>>>(eW2, cW1);
    precompute_kernel<<<Bb * Nn / 16, NT>>>(h, eW1, eb1);

    const int smem = (int)sizeof(ESmem);
    cudaFuncSetAttribute(edge_kernel, cudaFuncAttributeMaxDynamicSharedMemorySize, smem);
    dim3 grid(Nn, Bb);
    edge_kernel<<<grid, NT, smem>>>(x, eW1, eb2, cb1, cW2, xout);

    node_kernel<<<Bb * Nn, Hd>>>(h, nW1, nb1, nW2, nb2, hout);
}

// round 7
// speedup vs baseline: 8.3314x; 1.1038x over previous
#include <cuda_runtime.h>
#include <cuda_fp16.h>
#include <cstdint>

#define Hd 128
#define Nn 512
#define Bb 2
#define TJ 128
#define NT 256
#define LDK 136     // padded row stride in halfs: 68 words -> 4-bank shift/row, conflict-free
#define NTILES (Nn / TJ)

// ---------------- device scratch (no allocations allowed) ------------------
__device__ float g_A[Bb * Nn * Hd];      // h @ eW1[0:128] + eb1
__device__ float g_Bv[Bb * Nn * Hd];     // h @ eW1[128:256]
__device__ float g_magg[Bb * Nn * Hd];   // sum_j m_ij
__device__ uint4 g_W2h[2176];            // eW2^T f16 [n][k] pad LDK
__device__ uint4 g_C1h[2176];            // cW1^T f16 [n][k] pad LDK

__device__ __forceinline__ float tanh_f(float x) {
    float r;
    asm("tanh.approx.f32 %0, %1;" : "=f"(r) : "f"(x));
    return r;
}
// silu(x) = 0.5x * (1 + tanh(x/2))  -> single MUFU
__device__ __forceinline__ float silu_f(float v) {
    float h = 0.5f * v;
    return fmaf(h, tanh_f(h), h);
}
__device__ __forceinline__ uint32_t pk2(float a, float b) {
    __half2 h = __floats2half2_rn(a, b);
    return *reinterpret_cast<uint32_t*>(&h);
}
__device__ __forceinline__ void mma16816(float* c,
                                         uint32_t a0, uint32_t a1, uint32_t a2, uint32_t a3,
                                         uint32_t b0, uint32_t b1) {
    asm volatile(
        "mma.sync.aligned.m16n8k16.row.col.f32.f16.f16.f32 "
        "{%0,%1,%2,%3},{%4,%5,%6,%7},{%8,%9},{%0,%1,%2,%3};"
        : "+f"(c[0]), "+f"(c[1]), "+f"(c[2]), "+f"(c[3])
        : "r"(a0), "r"(a1), "r"(a2), "r"(a3), "r"(b0), "r"(b1));
}

// ---------------------------------------------------------------------------
// Weight conversion (once, tiny)
// ---------------------------------------------------------------------------
__global__ void convert_w_kernel(const float* __restrict__ eW2,
                                 const float* __restrict__ cW1) {
    int idx = blockIdx.x * blockDim.x + threadIdx.x;  // k*128+n
    if (idx >= Hd * Hd) return;
    int k = idx >> 7, n = idx & 127;
    ((__half*)g_W2h)[n * LDK + k] = __float2half(eW2[idx]);
    ((__half*)g_C1h)[n * LDK + k] = __float2half(cW1[idx]);
}

// ---------------------------------------------------------------------------
// Precompute A/Bv: 16 rows per CTA, 256 threads (k = t&127, sel = t>>7)
// ---------------------------------------------------------------------------
__global__ void precompute_kernel(const float* __restrict__ h,
                                  const float* __restrict__ eW1,
                                  const float* __restrict__ eb1) {
    __shared__ float sh[16][Hd];
    const int row0 = blockIdx.x * 16;
    const int t = threadIdx.x, k = t & 127, sel = t >> 7;
    for (int idx = t; idx < 16 * Hd; idx += NT)
        sh[idx >> 7][idx & 127] = h[row0 * Hd + idx];
    __syncthreads();
    float acc[16];
#pragma unroll
    for (int i = 0; i < 16; i++) acc[i] = sel ? 0.f : eb1[k];
    const float* w = eW1 + sel * Hd * Hd + k;
#pragma unroll 4
    for (int r = 0; r < Hd; r++) {
        float wv = w[r * Hd];
#pragma unroll
        for (int i = 0; i < 16; i++) acc[i] += sh[i][r] * wv;
    }
    float* dst = sel ? g_Bv : g_A;
#pragma unroll
    for (int i = 0; i < 16; i++) dst[(row0 + i) * Hd + k] = acc[i];
}

// ---------------------------------------------------------------------------
// Edge kernel: 1 CTA per (b,i); TJ=128; in-place T1; occ 2
// ---------------------------------------------------------------------------
struct __align__(16) ESmem {
    __half W2[Hd * LDK];   // eW2^T
    __half C1[Hd * LDK];   // cW1^T
    __half T1[TJ * LDK];   // activation tile (reused in place for m_ij)
    float sAi[Hd], sWd[Hd], sEb2[Hd], sCb1[Hd], sCw2[Hd];
    float SD[TJ];
    float sx3[TJ * 3];
    float P[2][TJ];
    float mred[4][Hd];
    float csum[4][3];
};

// acc[0..7]: rows rowbase..+15 ; acc[8..15]: rows rowbase+16..+31
__device__ __forceinline__ void gemm_acc(const __half* __restrict__ A,
                                         const __half* __restrict__ W,
                                         float acc[16][4],
                                         int g, int tig, int rowbase, int colbase) {
    const uint32_t* Au = reinterpret_cast<const uint32_t*>(A);
    const uint32_t* Wu = reinterpret_cast<const uint32_t*>(W);
    const int r00 = (rowbase + g) * (LDK / 2);
    const int r01 = (rowbase + g + 8) * (LDK / 2);
    const int r10 = (rowbase + 16 + g) * (LDK / 2);
    const int r11 = (rowbase + 24 + g) * (LDK / 2);
#pragma unroll
    for (int ks = 0; ks < 8; ks++) {
        const int kh = ks * 8;
        uint32_t a00 = Au[r00 + kh + tig];
        uint32_t a01 = Au[r01 + kh + tig];
        uint32_t a02 = Au[r00 + kh + 4 + tig];
        uint32_t a03 = Au[r01 + kh + 4 + tig];
        uint32_t a10 = Au[r10 + kh + tig];
        uint32_t a11 = Au[r11 + kh + tig];
        uint32_t a12 = Au[r10 + kh + 4 + tig];
        uint32_t a13 = Au[r11 + kh + 4 + tig];
#pragma unroll
        for (int nb = 0; nb < 8; nb++) {
            const int n = colbase + nb * 8 + g;
            const int wb = n * (LDK / 2) + kh;
            uint32_t b0 = Wu[wb + tig];
            uint32_t b1 = Wu[wb + 4 + tig];
            mma16816(acc[nb],     a00, a01, a02, a03, b0, b1);
            mma16816(acc[8 + nb], a10, a11, a12, a13, b0, b1);
        }
    }
}

__global__ void __launch_bounds__(NT, 2)
edge_kernel(const float* __restrict__ x,
            const float* __restrict__ eW1,
            const float* __restrict__ eb2, const float* __restrict__ cb1,
            const float* __restrict__ cW2,
            float* __restrict__ xout) {
    extern __shared__ __align__(16) unsigned char sm_raw[];
    ESmem* S = reinterpret_cast<ESmem*>(sm_raw);

    const int i = blockIdx.x, b = blockIdx.y;
    const int t = threadIdx.x;
    const int lane = t & 31, wid = t >> 5;
    const int g = lane >> 2, tig = lane & 3;
    const int rowbase = (wid & 3) * 32;   // 4 rowgroups of 32 rows
    const int colbase = (wid >> 2) * 64;  // 2 colgroups of 64 cols
    const int cg = wid >> 2;
    const int row_i = b * Nn + i;

    // weights: flat copies from pre-converted global
    {
        uint4* dw = (uint4*)S->W2;
        uint4* dc = (uint4*)S->C1;
        for (int idx = t; idx < 2176; idx += NT) {
            dw[idx] = g_W2h[idx];
            dc[idx] = g_C1h[idx];
        }
    }
    for (int idx = t; idx < Hd; idx += NT) {
        S->sAi[idx]  = g_A[row_i * Hd + idx];
        S->sWd[idx]  = eW1[256 * Hd + idx];
        S->sEb2[idx] = eb2[idx];
        S->sCb1[idx] = cb1[idx];
        S->sCw2[idx] = cW2[idx];
    }
    const float xi0 = x[row_i * 3 + 0];
    const float xi1 = x[row_i * 3 + 1];
    const float xi2 = x[row_i * 3 + 2];

    float macc[16];
#pragma unroll
    for (int c = 0; c < 16; c++) macc[c] = 0.f;
    float cx = 0.f, cy = 0.f, cz = 0.f;
    __syncthreads();

    for (int jt = 0; jt < NTILES; jt++) {
        const int j0 = jt * TJ;

        // Phase A: distances + x_j
        if (t < TJ) {
            const int j = j0 + t;
            float x0 = x[(b * Nn + j) * 3 + 0];
            float x1 = x[(b * Nn + j) * 3 + 1];
            float x2 = x[(b * Nn + j) * 3 + 2];
            S->sx3[t * 3 + 0] = x0; S->sx3[t * 3 + 1] = x1; S->sx3[t * 3 + 2] = x2;
            float dx = xi0 - x0, dy = xi1 - x1, dz = xi2 - x2;
            S->SD[t] = dx * dx + dy * dy + dz * dz;
        }
        __syncthreads();

        // Phase B: T1 = f16(silu(Ai + Bv_j + d*Wd)), 128x128
#pragma unroll
        for (int it = 0; it < 16; it++) {
            const int idx = t * 4 + it * NT * 4;
            const int m = idx >> 7, k = idx & 127;
            float4 bv = *(const float4*)&g_Bv[(size_t)(b * Nn + j0 + m) * Hd + k];
            const float d = S->SD[m];
            float v0 = silu_f(S->sAi[k + 0] + bv.x + d * S->sWd[k + 0]);
            float v1 = silu_f(S->sAi[k + 1] + bv.y + d * S->sWd[k + 1]);
            float v2 = silu_f(S->sAi[k + 2] + bv.z + d * S->sWd[k + 2]);
            float v3 = silu_f(S->sAi[k + 3] + bv.w + d * S->sWd[k + 3]);
            uint2 pk; pk.x = pk2(v0, v1); pk.y = pk2(v2, v3);
            *(uint2*)&S->T1[m * LDK + k] = pk;
        }
        __syncthreads();

        // GEMM1: acc = T1 @ eW2 (all reads of T1 complete before aliased write)
        {
            float acc[16][4];
#pragma unroll
            for (int q = 0; q < 16; q++)
#pragma unroll
                for (int c = 0; c < 4; c++) acc[q][c] = 0.f;
            gemm_acc(S->T1, S->W2, acc, g, tig, rowbase, colbase);
            __syncthreads();   // colgroup partner warp must finish reading these rows

            // Epilogue 1 (in place): T1 = f16(silu(acc + eb2)), magg += colsums
            const int r0 = rowbase + g, r1 = r0 + 8, r2 = r0 + 16, r3 = r0 + 24;
#pragma unroll
            for (int nb = 0; nb < 8; nb++) {
                const int col = colbase + nb * 8 + 2 * tig;
                const float bb0 = S->sEb2[col], bb1 = S->sEb2[col + 1];
                float v00 = silu_f(acc[nb][0] + bb0);
                float v01 = silu_f(acc[nb][1] + bb1);
                float v10 = silu_f(acc[nb][2] + bb0);
                float v11 = silu_f(acc[nb][3] + bb1);
                float v20 = silu_f(acc[8 + nb][0] + bb0);
                float v21 = silu_f(acc[8 + nb][1] + bb1);
                float v30 = silu_f(acc[8 + nb][2] + bb0);
                float v31 = silu_f(acc[8 + nb][3] + bb1);
                *(uint32_t*)&S->T1[r0 * LDK + col] = pk2(v00, v01);
                *(uint32_t*)&S->T1[r1 * LDK + col] = pk2(v10, v11);
                *(uint32_t*)&S->T1[r2 * LDK + col] = pk2(v20, v21);
                *(uint32_t*)&S->T1[r3 * LDK + col] = pk2(v30, v31);
                macc[2 * nb]     += v00 + v10 + v20 + v30;
                macc[2 * nb + 1] += v01 + v11 + v21 + v31;
            }
        }
        __syncthreads();

        // GEMM2 + fused dot: P[cg][row] = dot(silu(T1 @ cW1 + cb1), cW2)
        {
            float acc[16][4];
#pragma unroll
            for (int q = 0; q < 16; q++)
#pragma unroll
                for (int c = 0; c < 4; c++) acc[q][c] = 0.f;
            gemm_acc(S->T1, S->C1, acc, g, tig, rowbase, colbase);
            float d0 = 0.f, d1 = 0.f, d2 = 0.f, d3 = 0.f;
#pragma unroll
            for (int nb = 0; nb < 8; nb++) {
                const int col = colbase + nb * 8 + 2 * tig;
                const float w0 = S->sCw2[col], w1 = S->sCw2[col + 1];
                const float bb0 = S->sCb1[col], bb1 = S->sCb1[col + 1];
                d0 += silu_f(acc[nb][0] + bb0) * w0 + silu_f(acc[nb][1] + bb1) * w1;
                d1 += silu_f(acc[nb][2] + bb0) * w0 + silu_f(acc[nb][3] + bb1) * w1;
                d2 += silu_f(acc[8 + nb][0] + bb0) * w0 + silu_f(acc[8 + nb][1] + bb1) * w1;
                d3 += silu_f(acc[8 + nb][2] + bb0) * w0 + silu_f(acc[8 + nb][3] + bb1) * w1;
            }
            d0 += __shfl_xor_sync(0xffffffffu, d0, 1); d0 += __shfl_xor_sync(0xffffffffu, d0, 2);
            d1 += __shfl_xor_sync(0xffffffffu, d1, 1); d1 += __shfl_xor_sync(0xffffffffu, d1, 2);
            d2 += __shfl_xor_sync(0xffffffffu, d2, 1); d2 += __shfl_xor_sync(0xffffffffu, d2, 2);
            d3 += __shfl_xor_sync(0xffffffffu, d3, 1); d3 += __shfl_xor_sync(0xffffffffu, d3, 2);
            if (tig == 0) {
                S->P[cg][rowbase + g]      = d0;
                S->P[cg][rowbase + g + 8]  = d1;
                S->P[cg][rowbase + g + 16] = d2;
                S->P[cg][rowbase + g + 24] = d3;
            }
        }
        __syncthreads();

        // coord accumulation over this tile
        if (t < TJ) {
            float wv = tanh_f(S->P[0][t] + S->P[1][t]);
            cx += (xi0 - S->sx3[t * 3 + 0]) * wv;
            cy += (xi1 - S->sx3[t * 3 + 1]) * wv;
            cz += (xi2 - S->sx3[t * 3 + 2]) * wv;
        }
        __syncthreads();
    }

    // magg: reduce lanes sharing columns, store per rowgroup
#pragma unroll
    for (int c = 0; c < 16; c++) {
        macc[c] += __shfl_down_sync(0xffffffffu, macc[c], 4);
        macc[c] += __shfl_down_sync(0xffffffffu, macc[c], 8);
        macc[c] += __shfl_down_sync(0xffffffffu, macc[c], 16);
    }
    if (lane < 4) {
#pragma unroll
        for (int nb = 0; nb < 8; nb++) {
            const int col = colbase + nb * 8 + 2 * lane;
            S->mred[wid & 3][col]     = macc[2 * nb];
            S->mred[wid & 3][col + 1] = macc[2 * nb + 1];
        }
    }

    // coord cross-warp reduce
    if (t < TJ) {
#pragma unroll
        for (int off = 16; off; off >>= 1) {
            cx += __shfl_down_sync(0xffffffffu, cx, off);
            cy += __shfl_down_sync(0xffffffffu, cy, off);
            cz += __shfl_down_sync(0xffffffffu, cz, off);
        }
        if (lane == 0) { S->csum[wid][0] = cx; S->csum[wid][1] = cy; S->csum[wid][2] = cz; }
    }
    __syncthreads();

    if (t < Hd) {
        float s = S->mred[0][t] + S->mred[1][t] + S->mred[2][t] + S->mred[3][t];
        g_magg[row_i * Hd + t] = s;
    }
    if (t == 0) {
        const float inv = 1.0f / (float)(Nn - 1);
        float s0 = S->csum[0][0] + S->csum[1][0] + S->csum[2][0] + S->csum[3][0];
        float s1 = S->csum[0][1] + S->csum[1][1] + S->csum[2][1] + S->csum[3][1];
        float s2 = S->csum[0][2] + S->csum[1][2] + S->csum[2][2] + S->csum[3][2];
        xout[row_i * 3 + 0] = xi0 + s0 * inv;
        xout[row_i * 3 + 1] = xi1 + s1 * inv;
        xout[row_i * 3 + 2] = xi2 + s2 * inv;
    }
}

// ---------------------------------------------------------------------------
// Node MLP: 8 rows per CTA, 128 threads, register blocking
// ---------------------------------------------------------------------------
__global__ void node_kernel(const float* __restrict__ h,
                            const float* __restrict__ nW1, const float* __restrict__ nb1,
                            const float* __restrict__ nW2, const float* __restrict__ nb2,
                            float* __restrict__ hout) {
    __shared__ float sin_s[8][2 * Hd];
    __shared__ float st1[8][Hd];
    const int row0 = blockIdx.x * 8;
    const int k = threadIdx.x;  // 0..127
    for (int idx = k; idx < 8 * 2 * Hd; idx += Hd) {
        const int r = idx >> 8, c = idx & 255;
        sin_s[r][c] = (c < Hd) ? h[(row0 + r) * Hd + c]
                               : g_magg[(row0 + r) * Hd + (c - Hd)];
    }
    __syncthreads();
    float acc[8];
#pragma unroll
    for (int r = 0; r < 8; r++) acc[r] = nb1[k];
#pragma unroll 4
    for (int c = 0; c < 2 * Hd; c++) {
        const float w = nW1[c * Hd + k];
#pragma unroll
        for (int r = 0; r < 8; r++) acc[r] += sin_s[r][c] * w;
    }
#pragma unroll
    for (int r = 0; r < 8; r++) st1[r][k] = silu_f(acc[r]);
    __syncthreads();
    float o[8];
#pragma unroll
    for (int r = 0; r < 8; r++) o[r] = nb2[k];
#pragma unroll 4
    for (int c = 0; c < Hd; c++) {
        const float w = nW2[c * Hd + k];
#pragma unroll
        for (int r = 0; r < 8; r++) o[r] += st1[r][c] * w;
    }
#pragma unroll
    for (int r = 0; r < 8; r++) hout[(row0 + r) * Hd + k] = sin_s[r][k] + o[r];
}

// ---------------------------------------------------------------------------
extern "C" void kernel_launch(void* const* d_in, const int* in_sizes, int n_in,
                              void* d_out, int out_size) {
    const float* h   = (const float*)d_in[0];
    const float* x   = (const float*)d_in[1];
    const float* eW1 = (const float*)d_in[2];
    const float* eb1 = (const float*)d_in[3];
    const float* eW2 = (const float*)d_in[4];
    const float* eb2 = (const float*)d_in[5];
    const float* nW1 = (const float*)d_in[6];
    const float* nb1 = (const float*)d_in[7];
    const float* nW2 = (const float*)d_in[8];
    const float* nb2 = (const float*)d_in[9];
    const float* cW1 = (const float*)d_in[10];
    const float* cb1 = (const float*)d_in[11];
    const float* cW2 = (const float*)d_in[12];

    float* out  = (float*)d_out;
    float* hout = out;
    float* xout = out + Bb * Nn * Hd;

    convert_w_kernel<<<64, 256>>>(eW2, cW1);
    precompute_kernel<<<Bb * Nn / 16, NT>>>(h, eW1, eb1);

    const int smem = (int)sizeof(ESmem);
    cudaFuncSetAttribute(edge_kernel, cudaFuncAttributeMaxDynamicSharedMemorySize, smem);
    dim3 grid(Nn, Bb);
    edge_kernel<<<grid, NT, smem>>>(x, eW1, eb2, cb1, cW2, xout);

    node_kernel<<<Bb * Nn / 8, Hd>>>(h, nW1, nb1, nW2, nb2, hout);
}